// round 3
// baseline (speedup 1.0000x reference)
#include <cuda_runtime.h>
#include <math.h>

#define BB 32
#define SS 32
#define TT 31
#define HH 256
#define H3 768
#define VV 12000
#define NTOK 32
#define BOUND 16

// ---------------- metadata (written by control kernel) ----------------
__device__ signed char g_la[TT][BB];
__device__ signed char g_npop[TT][BB];
__device__ signed char g_pop_slot[TT][BB][SS];
__device__ signed char g_pop_tok[TT][BB][SS];
__device__ signed char g_spush_slot[TT][BB];   // -1 none
__device__ signed char g_spush_tok[TT][BB];    // -1 = rfinal value, >=0 token
__device__ signed char g_bpush_tok[TT][BB];    // -1 none
__device__ signed char g_stop[TT][BB];         // stack top after step

// precomputed token xw tables: set 0=a,1=b,2=s,3=r
__device__ __align__(16) float g_tokxw[4][NTOK][H3];
// attention outputs, row = b*TT + t
__device__ __align__(16) float g_att[BB * TT][HH];

// ---------------- control kernel: pure integer RNNG simulation ----------------
__global__ void control_kernel(const int* __restrict__ actions) {
    int b = threadIdx.x;
    int st = -1, tt_ = -1, bt = 0, acc = 1;  // bt=0 after initial buffer push
    signed char tm[SS];
    signed char stok[SS];

    for (int t = 0; t < TT; t++) {
        int a = actions[b * SS + t];
        int la = a * acc;
        int is_red = (la == 2) ? 1 : 0;
        int is_nt  = (la > 2 && la < BOUND) ? 1 : 0;
        int is_gen = (la >= BOUND) ? 1 : 0;

        // ---- reduce pops ----
        int np = 0;
        int ir = is_red, aok = 1;
        for (int i = 0; i < SS; i++) {
            if (!(ir && aok)) break;
            int can1 = (st >= 0);
            int pslot = -1;
            if (can1) { pslot = st; st--; }
            aok = aok & can1;
            int tag = 0;
            if (ir && aok) {
                int can2 = (tt_ >= 0);
                if (can2) { tag = tm[tt_]; tt_--; }
                aok = aok & can2;
            }
            int outm = ir & aok;
            if (outm) {
                g_pop_slot[t][b][np] = (signed char)pslot;
                g_pop_tok[t][b][np]  = stok[pslot];
                np++;
            }
            ir = (ir - tag) * aok;
        }
        int racc = aok;
        int sslot = -1, stokv = -2;
        // reduce pushes
        if (is_red && racc) {
            int can = (st + 1 < SS);
            if (can) { st++; sslot = st; stokv = -1; stok[st] = -1; }
            racc &= can;
            if (racc) {
                int can2 = (tt_ + 1 < SS);
                if (can2) { tt_++; tm[tt_] = 0; }
                racc &= can2;
            }
        }
        // global red_mult (cross-batch coupling)
        unsigned ball = __ballot_sync(0xffffffffu, is_red);
        int tot = np;
        for (int o = 16; o > 0; o >>= 1) tot += __shfl_xor_sync(0xffffffffu, tot, o);
        int red_mult = 1;
        if (ball) red_mult = (tot == 0) ? 0 : racc;
        acc *= red_mult;

        // ---- NT push ----
        if (is_nt) {
            int s5 = (st + 1 < SS);
            if (s5) { st++; stok[st] = (signed char)la; sslot = st; stokv = la; }
            acc *= s5;
            if (s5) {
                int s6 = (tt_ + 1 < SS);
                if (s6) { tt_++; tm[tt_] = 1; }
                acc *= s6;
            }
        }
        // ---- GEN push ----
        int bpush = -1;
        if (is_gen) {
            int s7 = (st + 1 < SS);
            if (s7) { st++; stok[st] = (signed char)la; sslot = st; stokv = la; }
            acc *= s7;
            int s8 = 1;
            if (s7) {
                s8 = (tt_ + 1 < SS);
                if (s8) { tt_++; tm[tt_] = 0; }
                acc *= s8;
            }
            if (s7 && s8) {
                int s9 = (bt + 1 < SS);
                if (s9) { bt++; bpush = la; }
                acc *= s9;
            }
        }
        g_bpush_tok[t][b]  = (signed char)bpush;
        g_la[t][b]         = (signed char)la;
        g_npop[t][b]       = (signed char)np;
        g_spush_slot[t][b] = (signed char)sslot;
        g_spush_tok[t][b]  = (signed char)stokv;
        g_stop[t][b]       = (signed char)st;
    }
}

// ---------------- token xw tables ----------------
__global__ void tokxw_kernel(const float* __restrict__ embed,
                             const float* __restrict__ aW, const float* __restrict__ ab,
                             const float* __restrict__ bW, const float* __restrict__ bb,
                             const float* __restrict__ sW, const float* __restrict__ sb,
                             const float* __restrict__ rW, const float* __restrict__ rb) {
    int tok = blockIdx.x;
    int set = blockIdx.y;
    const float* W  = (set == 0) ? aW : (set == 1) ? bW : (set == 2) ? sW : rW;
    const float* bi = (set == 0) ? ab : (set == 1) ? bb : (set == 2) ? sb : rb;
    int tid = threadIdx.x;  // 192 threads, 1 float4 col each
    const float4* W4 = (const float4*)W;
    float4 acc = __ldg((const float4*)bi + tid);
    const float* x = embed + (size_t)tok * HH;
#pragma unroll 8
    for (int k = 0; k < HH; k++) {
        float xk = __ldg(x + k);
        float4 w = __ldg(W4 + k * 192 + tid);
        acc.x += xk * w.x; acc.y += xk * w.y; acc.z += xk * w.z; acc.w += xk * w.w;
    }
    ((float4*)(&g_tokxw[set][tok][0]))[tid] = acc;
}

// ---------------- device helpers ----------------
// out[768] = x[256] @ M[256x768] (+bias). 192 active threads of 256, trailing sync.
__device__ __forceinline__ void mv768(const float* __restrict__ M, const float* __restrict__ x,
                                      float* out, const float* __restrict__ bias, int tid) {
    if (tid < 192) {
        const float4* M4 = (const float4*)M;
        float4 acc;
        if (bias) acc = __ldg((const float4*)bias + tid);
        else      acc = make_float4(0.f, 0.f, 0.f, 0.f);
#pragma unroll 8
        for (int k = 0; k < HH; k++) {
            float xk = x[k];
            float4 m = __ldg(M4 + k * 192 + tid);
            acc.x += xk * m.x; acc.y += xk * m.y; acc.z += xk * m.z; acc.w += xk * m.w;
        }
        ((float4*)out)[tid] = acc;
    }
    __syncthreads();
}

// 64-thread group matvec: 3 float4 columns per thread. No sync inside.
__device__ __forceinline__ void mv768_g64(const float* __restrict__ M, const float* __restrict__ x,
                                          float* out, const float* __restrict__ bias, int lt) {
    const float4* M4 = (const float4*)M;
    float4 a0, a1, a2;
    if (bias) {
        a0 = __ldg((const float4*)bias + lt);
        a1 = __ldg((const float4*)bias + 64 + lt);
        a2 = __ldg((const float4*)bias + 128 + lt);
    } else {
        a0 = a1 = a2 = make_float4(0.f, 0.f, 0.f, 0.f);
    }
#pragma unroll 4
    for (int k = 0; k < HH; k++) {
        float xk = x[k];
        float4 m0 = __ldg(M4 + k * 192 + lt);
        float4 m1 = __ldg(M4 + k * 192 + 64 + lt);
        float4 m2 = __ldg(M4 + k * 192 + 128 + lt);
        a0.x += xk * m0.x; a0.y += xk * m0.y; a0.z += xk * m0.z; a0.w += xk * m0.w;
        a1.x += xk * m1.x; a1.y += xk * m1.y; a1.z += xk * m1.z; a1.w += xk * m1.w;
        a2.x += xk * m2.x; a2.y += xk * m2.y; a2.z += xk * m2.z; a2.w += xk * m2.w;
    }
    ((float4*)out)[lt] = a0;
    ((float4*)out)[64 + lt] = a1;
    ((float4*)out)[128 + lt] = a2;
}

__device__ __forceinline__ float sigm(float v) { return 1.f / (1.f + expf(-v)); }

// GRU gate combine with trailing sync
__device__ __forceinline__ void gru_fin(const float* __restrict__ xw, const float* __restrict__ hu,
                                        const float* __restrict__ hprev, float* hout, int tid) {
    float xz = xw[tid], xr = xw[HH + tid], xn = xw[2 * HH + tid];
    float hz = 0.f, hr = 0.f, hn = 0.f, hp = 0.f;
    if (hu) { hz = hu[tid]; hr = hu[HH + tid]; hn = hu[2 * HH + tid]; }
    if (hprev) hp = hprev[tid];
    float z = sigm(xz + hz);
    float r = sigm(xr + hr);
    float n = tanhf(xn + r * hn);
    hout[tid] = (1.f - z) * hp + z * n;
    __syncthreads();
}

// one column of a [256,256] piece of Wc
__device__ __forceinline__ float dotcol256(const float* __restrict__ x,
                                           const float* __restrict__ W, int c) {
    float acc = 0.f;
#pragma unroll 8
    for (int k = 0; k < HH; k++) acc += x[k] * __ldg(W + (size_t)k * HH + c);
    return acc;
}

// ---------------- main sequential kernel: one CTA per batch element ----------------
extern __shared__ float smem_f[];
__global__ __launch_bounds__(256) void main_kernel(
    const float* __restrict__ aU, const float* __restrict__ bU,
    const float* __restrict__ sU, const float* __restrict__ rU,
    const float* __restrict__ sW, const float* __restrict__ sb,
    const float* __restrict__ rW, const float* __restrict__ rb,
    const float* __restrict__ Wc, const float* __restrict__ bc) {
    int b = blockIdx.x, tid = threadIdx.x;

    float* sm_v  = smem_f;             // [32][256]
    float* hs    = sm_v + SS * HH;     // [32][256]
    float* bufh  = hs + SS * HH;       // [256]
    float* ah    = bufh + HH;          // [256]
    float* hred  = ah + HH;            // [256]
    float* s_hu_a = hred + HH;         // [768]
    float* s_hu_b = s_hu_a + H3;       // [768]
    float* s_hu_s = s_hu_b + H3;       // [768]
    float* s_hu_r = s_hu_s + H3;       // [768]
    float* s_xw_r = s_hu_r + H3;       // [768]
    float* s_xw_s = s_xw_r + H3;       // [768]
    float* p_s    = s_xw_s + H3;       // [256]
    float* p_ah   = p_s + HH;          // [256]
    float* p_b    = p_ah + HH;         // [256]

    // initial buffer push: bufh = GRU_b(embed[START=1], 0)
    gru_fin(&g_tokxw[1][1][0], nullptr, nullptr, bufh, tid);

    int prev_stop = -1;
    p_s[tid] = 0.f;   // empty-stack piece
    __syncthreads();

    for (int t = 0; t < TT; t++) {
        int la    = g_la[t][b];
        int np    = g_npop[t][b];
        int sslot = g_spush_slot[t][b];
        int stokv = g_spush_tok[t][b];
        int bpush = g_bpush_tok[t][b];
        int stop  = g_stop[t][b];

        // ---- Phase A: chain-independent matvecs in 4 x 64-thread groups ----
        {
            int g = tid >> 6, lt = tid & 63;
            const float *M = nullptr, *xp = nullptr, *bi = nullptr;
            float* op = nullptr;
            if (g == 0) {
                if (t > 0) { M = aU; xp = ah; op = s_hu_a; }
            } else if (g == 1) {
                if (bpush >= 0) { M = bU; xp = bufh; op = s_hu_b; }
            } else if (g == 2) {
                if (sslot > 0) { M = sU; xp = &hs[(sslot - 1) * HH]; op = s_hu_s; }
            } else {
                if (np > 0) {
                    int tk = g_pop_tok[t][b][0];
                    if (tk < 0) {
                        M = rW; xp = &sm_v[(int)g_pop_slot[t][b][0] * HH];
                        bi = rb; op = s_xw_r;
                    }
                }
            }
            if (M) mv768_g64(M, xp, op, bi, lt);
            __syncthreads();
        }

        // ---- reduce chain ----
        for (int i = 0; i < np; i++) {
            int slot = g_pop_slot[t][b][i];
            int tok  = g_pop_tok[t][b][i];
            const float* xw;
            if (tok >= 0) xw = &g_tokxw[3][tok][0];
            else if (i == 0) xw = s_xw_r;
            else { mv768(rW, &sm_v[slot * HH], s_xw_r, rb, tid); xw = s_xw_r; }
            if (i > 0) mv768(rU, hred, s_hu_r, nullptr, tid);
            gru_fin(xw, (i > 0) ? s_hu_r : nullptr, (i > 0) ? hred : nullptr, hred, tid);
        }

        // ---- sW@hred for reduce-result push (also record value on stack) ----
        bool redpush = (sslot >= 0 && stokv == -1);
        if (redpush) {
            sm_v[sslot * HH + tid] = hred[tid];
            mv768(sW, hred, s_xw_s, sb, tid);  // trailing sync
        }

        // ---- all gate combines (stack push / buffer push / action), one sync ----
        {
            int c = tid;
            if (sslot >= 0) {
                const float* xw = (stokv >= 0) ? &g_tokxw[2][stokv][0] : s_xw_s;
                float hz = 0.f, hr = 0.f, hn = 0.f, hp = 0.f;
                if (sslot > 0) {
                    hz = s_hu_s[c]; hr = s_hu_s[HH + c]; hn = s_hu_s[2 * HH + c];
                    hp = hs[(sslot - 1) * HH + c];
                }
                float z = sigm(xw[c] + hz);
                float r = sigm(xw[HH + c] + hr);
                float n = tanhf(xw[2 * HH + c] + r * hn);
                hs[sslot * HH + c] = (1.f - z) * hp + z * n;
            }
            if (bpush >= 0) {
                const float* xw = &g_tokxw[1][bpush][0];
                float hz = s_hu_b[c], hr = s_hu_b[HH + c], hn = s_hu_b[2 * HH + c];
                float hp = bufh[c];
                float z = sigm(xw[c] + hz);
                float r = sigm(xw[HH + c] + hr);
                float n = tanhf(xw[2 * HH + c] + r * hn);
                bufh[c] = (1.f - z) * hp + z * n;
            }
            {
                const float* xw = &g_tokxw[0][la][0];
                float hz = 0.f, hr = 0.f, hn = 0.f, hp = 0.f;
                if (t > 0) {
                    hz = s_hu_a[c]; hr = s_hu_a[HH + c]; hn = s_hu_a[2 * HH + c];
                    hp = ah[c];
                }
                float z = sigm(xw[c] + hz);
                float r = sigm(xw[HH + c] + hr);
                float n = tanhf(xw[2 * HH + c] + r * hn);
                ah[c] = (1.f - z) * hp + z * n;
            }
        }
        __syncthreads();

        // ---- attention with dirty-tracked pieces ----
        {
            bool s_dirty = (stop != prev_stop) || (sslot >= 0);
            if (s_dirty) {
                if (stop < 0) p_s[tid] = 0.f;
                else p_s[tid] = dotcol256(&hs[stop * HH], Wc, tid);
            }
            p_ah[tid] = dotcol256(ah, Wc + (size_t)HH * HH, tid);
            if (t == 0 || bpush >= 0)
                p_b[tid] = dotcol256(bufh, Wc + (size_t)2 * HH * HH, tid);
            float v = p_s[tid] + p_ah[tid] + p_b[tid] + __ldg(bc + tid);
            g_att[b * TT + t][tid] = tanhf(v);
            prev_stop = stop;
        }
        __syncthreads();
    }
}

// ---------------- logits GEMM: [992,256] @ [256,12000] + bp ----------------
#define GBM 128
#define GBN 128
#define GBK 16
__global__ __launch_bounds__(256, 2) void gemm_kernel(const float* __restrict__ Wp,
                                                      const float* __restrict__ bp,
                                                      float* __restrict__ out) {
    __shared__ float As[GBK][GBM];  // 8 KB, transposed
    __shared__ float Bs[GBK][GBN];  // 8 KB
    int tid = threadIdx.x;
    int c0 = blockIdx.x * GBN;
    int row0 = blockIdx.y * GBM;
    const float* A = (const float*)g_att;
    const int MROWS = BB * TT;  // 992

    int ty = tid >> 4, tx = tid & 15;  // 16x16 threads, 8x8 micro-tile

    float acc[8][8];
#pragma unroll
    for (int i = 0; i < 8; i++)
#pragma unroll
        for (int j = 0; j < 8; j++) acc[i][j] = 0.f;

    for (int kk = 0; kk < HH; kk += GBK) {
        // load A tile (transposed into As[k][m])
#pragma unroll
        for (int i = 0; i < 2; i++) {
            int lin = tid * 2 + i;           // 0..511
            int row = lin >> 2;              // 0..127
            int kq  = lin & 3;               // 0..3
            int grow = row0 + row;
            float4 v = make_float4(0.f, 0.f, 0.f, 0.f);
            if (grow < MROWS)
                v = __ldg((const float4*)(A + (size_t)grow * HH + kk + kq * 4));
            As[kq * 4 + 0][row] = v.x;
            As[kq * 4 + 1][row] = v.y;
            As[kq * 4 + 2][row] = v.z;
            As[kq * 4 + 3][row] = v.w;
        }
        // load B tile
#pragma unroll
        for (int i = 0; i < 2; i++) {
            int lin = tid * 2 + i;           // 0..511
            int kr = lin >> 5;               // 0..15
            int cq = lin & 31;               // 0..31
            int gc = c0 + cq * 4;
            float4 v = make_float4(0.f, 0.f, 0.f, 0.f);
            if (gc + 3 < VV)
                v = __ldg((const float4*)(Wp + (size_t)(kk + kr) * VV + gc));
            *((float4*)&Bs[kr][cq * 4]) = v;
        }
        __syncthreads();
#pragma unroll
        for (int k = 0; k < GBK; k++) {
            float4 a01 = *((const float4*)&As[k][ty * 8]);
            float4 a23 = *((const float4*)&As[k][ty * 8 + 4]);
            float4 b01 = *((const float4*)&Bs[k][tx * 8]);
            float4 b23 = *((const float4*)&Bs[k][tx * 8 + 4]);
            float ar[8] = {a01.x, a01.y, a01.z, a01.w, a23.x, a23.y, a23.z, a23.w};
            float br[8] = {b01.x, b01.y, b01.z, b01.w, b23.x, b23.y, b23.z, b23.w};
#pragma unroll
            for (int i = 0; i < 8; i++)
#pragma unroll
                for (int j = 0; j < 8; j++) acc[i][j] += ar[i] * br[j];
        }
        __syncthreads();
    }

    // epilogue: bias + store
    float bias[8];
#pragma unroll
    for (int j = 0; j < 8; j++) {
        int gc = c0 + tx * 8 + j;
        bias[j] = (gc < VV) ? __ldg(bp + gc) : 0.f;
    }
#pragma unroll
    for (int i = 0; i < 8; i++) {
        int grow = row0 + ty * 8 + i;
        if (grow >= MROWS) continue;
        int gc = c0 + tx * 8;
        if (gc + 7 < VV) {
            float4 o0 = make_float4(acc[i][0] + bias[0], acc[i][1] + bias[1],
                                    acc[i][2] + bias[2], acc[i][3] + bias[3]);
            float4 o1 = make_float4(acc[i][4] + bias[4], acc[i][5] + bias[5],
                                    acc[i][6] + bias[6], acc[i][7] + bias[7]);
            *((float4*)(out + (size_t)grow * VV + gc)) = o0;
            *((float4*)(out + (size_t)grow * VV + gc + 4)) = o1;
        } else {
#pragma unroll
            for (int j = 0; j < 8; j++)
                if (gc + j < VV) out[(size_t)grow * VV + gc + j] = acc[i][j] + bias[j];
        }
    }
}

// ---------------- argmax per row ----------------
__global__ void argmax_kernel(const float* __restrict__ logits, float* __restrict__ preds) {
    int row = blockIdx.x;
    int tid = threadIdx.x;
    const float* p = logits + (size_t)row * VV;
    float best = -3.4e38f;
    int bi = VV;
    for (int c = tid; c < VV; c += 256) {
        float v = p[c];
        if (v > best) { best = v; bi = c; }
    }
    __shared__ float sv[256];
    __shared__ int si[256];
    sv[tid] = best; si[tid] = bi;
    __syncthreads();
    for (int o = 128; o > 0; o >>= 1) {
        if (tid < o) {
            if (sv[tid + o] > sv[tid] || (sv[tid + o] == sv[tid] && si[tid + o] < si[tid])) {
                sv[tid] = sv[tid + o]; si[tid] = si[tid + o];
            }
        }
        __syncthreads();
    }
    if (tid == 0) preds[row] = (float)si[0];
}

// ---------------- launch ----------------
extern "C" void kernel_launch(void* const* d_in, const int* in_sizes, int n_in,
                              void* d_out, int out_size) {
    const int*   actions = (const int*)d_in[0];
    const float* embed = (const float*)d_in[1];
    const float* aW = (const float*)d_in[2];
    const float* aU = (const float*)d_in[3];
    const float* ab = (const float*)d_in[4];
    const float* bW = (const float*)d_in[5];
    const float* bU = (const float*)d_in[6];
    const float* bb = (const float*)d_in[7];
    const float* sW = (const float*)d_in[8];
    const float* sU = (const float*)d_in[9];
    const float* sb = (const float*)d_in[10];
    const float* rW = (const float*)d_in[11];
    const float* rU = (const float*)d_in[12];
    const float* rb = (const float*)d_in[13];
    const float* Wc = (const float*)d_in[14];
    const float* bc = (const float*)d_in[15];
    const float* Wp = (const float*)d_in[16];
    const float* bp = (const float*)d_in[17];

    float* outf = (float*)d_out;
    size_t nl = (size_t)BB * TT * VV;
    float* preds = nullptr;
    float* logits;
    if ((size_t)out_size >= nl + (size_t)BB * TT) {
        preds = outf;
        logits = outf + BB * TT;
    } else {
        logits = outf;
    }

    control_kernel<<<1, 32>>>(actions);
    tokxw_kernel<<<dim3(NTOK, 4), 192>>>(embed, aW, ab, bW, bb, sW, sb, rW, rb);

    size_t shbytes = (size_t)(SS * HH * 2 + HH * 3 + H3 * 6 + HH * 3) * sizeof(float);
    cudaFuncSetAttribute(main_kernel, cudaFuncAttributeMaxDynamicSharedMemorySize, (int)shbytes);
    main_kernel<<<BB, 256, shbytes>>>(aU, bU, sU, rU, sW, sb, rW, rb, Wc, bc);

    dim3 gg((VV + GBN - 1) / GBN, (BB * TT + GBM - 1) / GBM);
    gemm_kernel<<<gg, 256>>>(Wp, bp, logits);
    if (preds) argmax_kernel<<<BB * TT, 256>>>(logits, preds);
}

// round 4
// speedup vs baseline: 4.7511x; 4.7511x over previous
#include <cuda_runtime.h>
#include <math.h>

#define BB 32
#define SS 32
#define TT 31
#define HH 256
#define H3 768
#define VV 12000
#define NTOK 32
#define BOUND 16

// ---------------- metadata (written by control kernel) ----------------
__device__ signed char g_la[TT][BB];
__device__ signed char g_npop[TT][BB];
__device__ signed char g_pop_slot[TT][BB][SS];
__device__ signed char g_pop_tok[TT][BB][SS];
__device__ signed char g_spush_slot[TT][BB];   // -1 none
__device__ signed char g_spush_tok[TT][BB];    // -1 = rfinal value, >=0 token
__device__ signed char g_bpush_tok[TT][BB];    // -1 none
__device__ signed char g_stop[TT][BB];         // stack top after step

// precomputed token xw tables: set 0=a,1=b,2=s,3=r
__device__ __align__(16) float g_tokxw[4][NTOK][H3];
// attention outputs, row = b*TT + t
__device__ __align__(16) float g_att[BB * TT][HH];

// ---------------- f32x2 packed helpers ----------------
__device__ __forceinline__ unsigned long long pk2(float lo, float hi) {
    unsigned long long r;
    asm("mov.b64 %0, {%1, %2};" : "=l"(r) : "f"(lo), "f"(hi));
    return r;
}
__device__ __forceinline__ void upk2(float& lo, float& hi, unsigned long long v) {
    asm("mov.b64 {%0, %1}, %2;" : "=f"(lo), "=f"(hi) : "l"(v));
}
__device__ __forceinline__ void ffma2(unsigned long long& d, unsigned long long a,
                                      unsigned long long b) {
    asm("fma.rn.f32x2 %0, %1, %2, %3;" : "=l"(d) : "l"(a), "l"(b), "l"(d));
}

// ---------------- control kernel: pure integer RNNG simulation ----------------
__global__ void control_kernel(const int* __restrict__ actions) {
    int b = threadIdx.x;
    int st = -1, tt_ = -1, bt = 0, acc = 1;  // bt=0 after initial buffer push
    signed char tm[SS];
    signed char stok[SS];

    for (int t = 0; t < TT; t++) {
        int a = actions[b * SS + t];
        int la = a * acc;
        int is_red = (la == 2) ? 1 : 0;
        int is_nt  = (la > 2 && la < BOUND) ? 1 : 0;
        int is_gen = (la >= BOUND) ? 1 : 0;

        // ---- reduce pops ----
        int np = 0;
        int ir = is_red, aok = 1;
        for (int i = 0; i < SS; i++) {
            if (!(ir && aok)) break;
            int can1 = (st >= 0);
            int pslot = -1;
            if (can1) { pslot = st; st--; }
            aok = aok & can1;
            int tag = 0;
            if (ir && aok) {
                int can2 = (tt_ >= 0);
                if (can2) { tag = tm[tt_]; tt_--; }
                aok = aok & can2;
            }
            int outm = ir & aok;
            if (outm) {
                g_pop_slot[t][b][np] = (signed char)pslot;
                g_pop_tok[t][b][np]  = stok[pslot];
                np++;
            }
            ir = (ir - tag) * aok;
        }
        int racc = aok;
        int sslot = -1, stokv = -2;
        // reduce pushes
        if (is_red && racc) {
            int can = (st + 1 < SS);
            if (can) { st++; sslot = st; stokv = -1; stok[st] = -1; }
            racc &= can;
            if (racc) {
                int can2 = (tt_ + 1 < SS);
                if (can2) { tt_++; tm[tt_] = 0; }
                racc &= can2;
            }
        }
        // global red_mult (cross-batch coupling)
        unsigned ball = __ballot_sync(0xffffffffu, is_red);
        int tot = np;
        for (int o = 16; o > 0; o >>= 1) tot += __shfl_xor_sync(0xffffffffu, tot, o);
        int red_mult = 1;
        if (ball) red_mult = (tot == 0) ? 0 : racc;
        acc *= red_mult;

        // ---- NT push ----
        if (is_nt) {
            int s5 = (st + 1 < SS);
            if (s5) { st++; stok[st] = (signed char)la; sslot = st; stokv = la; }
            acc *= s5;
            if (s5) {
                int s6 = (tt_ + 1 < SS);
                if (s6) { tt_++; tm[tt_] = 1; }
                acc *= s6;
            }
        }
        // ---- GEN push ----
        int bpush = -1;
        if (is_gen) {
            int s7 = (st + 1 < SS);
            if (s7) { st++; stok[st] = (signed char)la; sslot = st; stokv = la; }
            acc *= s7;
            int s8 = 1;
            if (s7) {
                s8 = (tt_ + 1 < SS);
                if (s8) { tt_++; tm[tt_] = 0; }
                acc *= s8;
            }
            if (s7 && s8) {
                int s9 = (bt + 1 < SS);
                if (s9) { bt++; bpush = la; }
                acc *= s9;
            }
        }
        g_bpush_tok[t][b]  = (signed char)bpush;
        g_la[t][b]         = (signed char)la;
        g_npop[t][b]       = (signed char)np;
        g_spush_slot[t][b] = (signed char)sslot;
        g_spush_tok[t][b]  = (signed char)stokv;
        g_stop[t][b]       = (signed char)st;
    }
}

// ---------------- token xw tables ----------------
__global__ void tokxw_kernel(const float* __restrict__ embed,
                             const float* __restrict__ aW, const float* __restrict__ ab,
                             const float* __restrict__ bW, const float* __restrict__ bb,
                             const float* __restrict__ sW, const float* __restrict__ sb,
                             const float* __restrict__ rW, const float* __restrict__ rb) {
    int tok = blockIdx.x;
    int set = blockIdx.y;
    const float* W  = (set == 0) ? aW : (set == 1) ? bW : (set == 2) ? sW : rW;
    const float* bi = (set == 0) ? ab : (set == 1) ? bb : (set == 2) ? sb : rb;
    int tid = threadIdx.x;  // 192 threads, 1 float4 col each
    const float4* W4 = (const float4*)W;
    float4 acc = __ldg((const float4*)bi + tid);
    const float* x = embed + (size_t)tok * HH;
#pragma unroll 8
    for (int k = 0; k < HH; k++) {
        float xk = __ldg(x + k);
        float4 w = __ldg(W4 + k * 192 + tid);
        acc.x += xk * w.x; acc.y += xk * w.y; acc.z += xk * w.z; acc.w += xk * w.w;
    }
    ((float4*)(&g_tokxw[set][tok][0]))[tid] = acc;
}

// ---------------- device helpers ----------------
// out[768] = x[256] @ M[256x768] (+bias). 8-warp k-split: warp w handles k in
// [w*32, w*32+32), all 192 float4 columns. Partials reduced through smem.
__device__ __forceinline__ void mv768(const float* __restrict__ M, const float* __restrict__ x,
                                      float* out, const float* __restrict__ bias, int tid,
                                      float* part) {
    __syncthreads();  // protect scratch from previous use
    int w = tid >> 5, l = tid & 31;
    const float4* M4 = (const float4*)M + (size_t)(w * 32) * 192;
    const float* xw_ = x + w * 32;
    float4 a0 = make_float4(0.f, 0.f, 0.f, 0.f), a1 = a0, a2 = a0, a3 = a0, a4 = a0, a5 = a0;
#pragma unroll 2
    for (int k = 0; k < 32; k++) {
        float xk = xw_[k];
        const float4* row = M4 + k * 192;
        float4 m0 = __ldg(row + l);
        float4 m1 = __ldg(row + 32 + l);
        float4 m2 = __ldg(row + 64 + l);
        float4 m3 = __ldg(row + 96 + l);
        float4 m4 = __ldg(row + 128 + l);
        float4 m5 = __ldg(row + 160 + l);
        a0.x += xk * m0.x; a0.y += xk * m0.y; a0.z += xk * m0.z; a0.w += xk * m0.w;
        a1.x += xk * m1.x; a1.y += xk * m1.y; a1.z += xk * m1.z; a1.w += xk * m1.w;
        a2.x += xk * m2.x; a2.y += xk * m2.y; a2.z += xk * m2.z; a2.w += xk * m2.w;
        a3.x += xk * m3.x; a3.y += xk * m3.y; a3.z += xk * m3.z; a3.w += xk * m3.w;
        a4.x += xk * m4.x; a4.y += xk * m4.y; a4.z += xk * m4.z; a4.w += xk * m4.w;
        a5.x += xk * m5.x; a5.y += xk * m5.y; a5.z += xk * m5.z; a5.w += xk * m5.w;
    }
    float4* p4 = (float4*)part + w * 192;
    p4[l] = a0; p4[32 + l] = a1; p4[64 + l] = a2;
    p4[96 + l] = a3; p4[128 + l] = a4; p4[160 + l] = a5;
    __syncthreads();
#pragma unroll
    for (int m = 0; m < 3; m++) {
        int c = tid + m * 256;
        float s = bias ? __ldg(bias + c) : 0.f;
#pragma unroll
        for (int w2 = 0; w2 < 8; w2++) s += part[w2 * H3 + c];
        out[c] = s;
    }
    __syncthreads();
}

// out[256] = x[256] @ W[256x256]   (one attention piece), 8-warp k-split
__device__ __forceinline__ void piece_mv(const float* __restrict__ W, const float* __restrict__ x,
                                         float* out, int tid, float* part) {
    __syncthreads();  // protect scratch
    int w = tid >> 5, l = tid & 31;
    const float4* W4 = (const float4*)W + (size_t)(w * 32) * 64;
    const float* xw_ = x + w * 32;
    float4 a0 = make_float4(0.f, 0.f, 0.f, 0.f), a1 = a0;
#pragma unroll 4
    for (int k = 0; k < 32; k++) {
        float xk = xw_[k];
        const float4* row = W4 + k * 64;
        float4 m0 = __ldg(row + l);
        float4 m1 = __ldg(row + 32 + l);
        a0.x += xk * m0.x; a0.y += xk * m0.y; a0.z += xk * m0.z; a0.w += xk * m0.w;
        a1.x += xk * m1.x; a1.y += xk * m1.y; a1.z += xk * m1.z; a1.w += xk * m1.w;
    }
    float4* p4 = (float4*)part + w * 64;
    p4[l] = a0; p4[32 + l] = a1;
    __syncthreads();
    float s = 0.f;
#pragma unroll
    for (int w2 = 0; w2 < 8; w2++) s += part[w2 * HH + tid];
    out[tid] = s;   // same-thread read later; scratch reuse guarded by next start-sync
}

__device__ __forceinline__ float sigm(float v) { return 1.f / (1.f + expf(-v)); }

// GRU gate combine with trailing sync
__device__ __forceinline__ void gru_fin(const float* __restrict__ xw, const float* __restrict__ hu,
                                        const float* __restrict__ hprev, float* hout, int tid) {
    float xz = xw[tid], xr = xw[HH + tid], xn = xw[2 * HH + tid];
    float hz = 0.f, hr = 0.f, hn = 0.f, hp = 0.f;
    if (hu) { hz = hu[tid]; hr = hu[HH + tid]; hn = hu[2 * HH + tid]; }
    if (hprev) hp = hprev[tid];
    float z = sigm(xz + hz);
    float r = sigm(xr + hr);
    float n = tanhf(xn + r * hn);
    hout[tid] = (1.f - z) * hp + z * n;
    __syncthreads();
}

// ---------------- main sequential kernel: one CTA per batch element ----------------
extern __shared__ float smem_f[];
__global__ __launch_bounds__(256) void main_kernel(
    const float* __restrict__ aU, const float* __restrict__ bU,
    const float* __restrict__ sU, const float* __restrict__ rU,
    const float* __restrict__ sW, const float* __restrict__ sb,
    const float* __restrict__ rW, const float* __restrict__ rb,
    const float* __restrict__ Wc, const float* __restrict__ bc) {
    int b = blockIdx.x, tid = threadIdx.x;

    float* sm_v = smem_f;            // [32][256] stack values (only rfinal slots read)
    float* hs   = sm_v + SS * HH;    // [32][256] hidden-state stack
    float* bufh = hs + SS * HH;      // [256]
    float* ah   = bufh + HH;         // [256]
    float* hred = ah + HH;           // [256]
    float* s_hu = hred + HH;         // [768]
    float* s_xw = s_hu + H3;         // [768]
    float* part = s_xw + H3;         // [8*768] scratch
    float* p_s  = part + 8 * H3;     // [256]
    float* p_ah = p_s + HH;          // [256]
    float* p_b  = p_ah + HH;         // [256]

    // initial buffer push: bufh = GRU_b(embed[START=1], 0)  (hu=0 -> no U read)
    gru_fin(&g_tokxw[1][1][0], nullptr, nullptr, bufh, tid);
    bool ah_init = false;
    int prev_stop = -1;
    p_s[tid] = 0.f;   // empty-stack piece

    for (int t = 0; t < TT; t++) {
        int la    = g_la[t][b];
        int np    = g_npop[t][b];
        int sslot = g_spush_slot[t][b];
        int stokv = g_spush_tok[t][b];
        int bpush = g_bpush_tok[t][b];
        int stop  = g_stop[t][b];

        // ---- reduce GRU over popped values ----
        for (int i = 0; i < np; i++) {
            int slot = g_pop_slot[t][b][i];
            int tok  = g_pop_tok[t][b][i];
            const float* xw;
            if (tok >= 0) {
                xw = &g_tokxw[3][tok][0];
            } else {
                mv768(rW, &sm_v[slot * HH], s_xw, rb, tid, part);
                xw = s_xw;
            }
            const float* hp = (i == 0) ? nullptr : hred;
            if (hp) mv768(rU, hp, s_hu, nullptr, tid, part);
            gru_fin(xw, hp ? s_hu : nullptr, hp, hred, tid);
        }

        // ---- stack push (reduce result / NT / GEN) ----
        if (sslot >= 0) {
            const float* xw;
            if (stokv >= 0) {
                xw = &g_tokxw[2][stokv][0];
            } else {
                sm_v[sslot * HH + tid] = hred[tid];
                __syncthreads();
                mv768(sW, hred, s_xw, sb, tid, part);
                xw = s_xw;
            }
            const float* hp = (sslot > 0) ? &hs[(sslot - 1) * HH] : nullptr;
            if (hp) mv768(sU, hp, s_hu, nullptr, tid, part);
            gru_fin(xw, hp ? s_hu : nullptr, hp, &hs[sslot * HH], tid);
        }

        // ---- buffer push (GEN) ----
        if (bpush >= 0) {
            mv768(bU, bufh, s_hu, nullptr, tid, part);
            gru_fin(&g_tokxw[1][bpush][0], s_hu, bufh, bufh, tid);
        }

        // ---- action GRU (always) ----
        {
            const float* hp = ah_init ? ah : nullptr;
            if (hp) mv768(aU, hp, s_hu, nullptr, tid, part);
            gru_fin(&g_tokxw[0][la][0], hp ? s_hu : nullptr, hp, ah, tid);
            ah_init = true;
        }

        // ---- attention with dirty-tracked [256,256] pieces of Wc ----
        {
            bool s_dirty = (stop != prev_stop) || (sslot >= 0);   // uniform per CTA
            if (s_dirty) {
                if (stop < 0) { __syncthreads(); p_s[tid] = 0.f; }
                else piece_mv(Wc, &hs[stop * HH], p_s, tid, part);
            }
            piece_mv(Wc + (size_t)HH * H3 / 3 * 1, ah, p_ah, tid, part);   // rows 256..511
            if (t == 0 || bpush >= 0)
                piece_mv(Wc + (size_t)2 * HH * HH, bufh, p_b, tid, part);  // rows 512..767
            float v = p_s[tid] + p_ah[tid] + p_b[tid] + __ldg(bc + tid);
            g_att[b * TT + t][tid] = tanhf(v);
            prev_stop = stop;
        }
        __syncthreads();
    }
}

// ---------------- logits GEMM: [992,256] @ [256,12000] + bp, fma.rn.f32x2 ----------------
#define GBM 128
#define GBN 128
#define GBK 16
__global__ __launch_bounds__(256, 2) void gemm_kernel(const float* __restrict__ Wp,
                                                      const float* __restrict__ bp,
                                                      float* __restrict__ out) {
    __shared__ float As[GBK][GBM];  // transposed
    __shared__ float Bs[GBK][GBN];
    int tid = threadIdx.x;
    int c0 = blockIdx.x * GBN;
    int row0 = blockIdx.y * GBM;
    const float* A = (const float*)g_att;
    const int MROWS = BB * TT;  // 992

    int ty = tid >> 4, tx = tid & 15;  // 16x16 threads, 8x8 micro-tile

    unsigned long long accp[8][4];
#pragma unroll
    for (int i = 0; i < 8; i++)
#pragma unroll
        for (int j = 0; j < 4; j++) accp[i][j] = 0ull;

    for (int kk = 0; kk < HH; kk += GBK) {
#pragma unroll
        for (int i = 0; i < 2; i++) {
            int lin = tid * 2 + i;           // 0..511
            int row = lin >> 2;              // 0..127
            int kq  = lin & 3;               // 0..3
            int grow = row0 + row;
            float4 v = make_float4(0.f, 0.f, 0.f, 0.f);
            if (grow < MROWS)
                v = __ldg((const float4*)(A + (size_t)grow * HH + kk + kq * 4));
            As[kq * 4 + 0][row] = v.x;
            As[kq * 4 + 1][row] = v.y;
            As[kq * 4 + 2][row] = v.z;
            As[kq * 4 + 3][row] = v.w;
        }
#pragma unroll
        for (int i = 0; i < 2; i++) {
            int lin = tid * 2 + i;
            int kr = lin >> 5;               // 0..15
            int cq = lin & 31;               // 0..31
            int gc = c0 + cq * 4;
            float4 v = make_float4(0.f, 0.f, 0.f, 0.f);
            if (gc + 3 < VV)
                v = __ldg((const float4*)(Wp + (size_t)(kk + kr) * VV + gc));
            *((float4*)&Bs[kr][cq * 4]) = v;
        }
        __syncthreads();
#pragma unroll
        for (int k = 0; k < GBK; k++) {
            float4 a01 = *((const float4*)&As[k][ty * 8]);
            float4 a23 = *((const float4*)&As[k][ty * 8 + 4]);
            float4 b01 = *((const float4*)&Bs[k][tx * 8]);
            float4 b23 = *((const float4*)&Bs[k][tx * 8 + 4]);
            unsigned long long brp[4];
            brp[0] = pk2(b01.x, b01.y); brp[1] = pk2(b01.z, b01.w);
            brp[2] = pk2(b23.x, b23.y); brp[3] = pk2(b23.z, b23.w);
            float ar[8] = {a01.x, a01.y, a01.z, a01.w, a23.x, a23.y, a23.z, a23.w};
#pragma unroll
            for (int i = 0; i < 8; i++) {
                unsigned long long ap = pk2(ar[i], ar[i]);
                ffma2(accp[i][0], ap, brp[0]);
                ffma2(accp[i][1], ap, brp[1]);
                ffma2(accp[i][2], ap, brp[2]);
                ffma2(accp[i][3], ap, brp[3]);
            }
        }
        __syncthreads();
    }

    // epilogue: bias + store
    float bias[8];
#pragma unroll
    for (int j = 0; j < 8; j++) {
        int gc = c0 + tx * 8 + j;
        bias[j] = (gc < VV) ? __ldg(bp + gc) : 0.f;
    }
#pragma unroll
    for (int i = 0; i < 8; i++) {
        int grow = row0 + ty * 8 + i;
        if (grow >= MROWS) continue;
        int gc = c0 + tx * 8;
        float acc[8];
#pragma unroll
        for (int j = 0; j < 4; j++) upk2(acc[2 * j], acc[2 * j + 1], accp[i][j]);
        if (gc + 7 < VV) {
            float4 o0 = make_float4(acc[0] + bias[0], acc[1] + bias[1],
                                    acc[2] + bias[2], acc[3] + bias[3]);
            float4 o1 = make_float4(acc[4] + bias[4], acc[5] + bias[5],
                                    acc[6] + bias[6], acc[7] + bias[7]);
            *((float4*)(out + (size_t)grow * VV + gc)) = o0;
            *((float4*)(out + (size_t)grow * VV + gc + 4)) = o1;
        } else {
#pragma unroll
            for (int j = 0; j < 8; j++)
                if (gc + j < VV) out[(size_t)grow * VV + gc + j] = acc[j] + bias[j];
        }
    }
}

// ---------------- argmax per row ----------------
__global__ void argmax_kernel(const float* __restrict__ logits, float* __restrict__ preds) {
    int row = blockIdx.x;
    int tid = threadIdx.x;
    const float* p = logits + (size_t)row * VV;
    float best = -3.4e38f;
    int bi = VV;
    for (int c = tid; c < VV; c += 256) {
        float v = p[c];
        if (v > best) { best = v; bi = c; }
    }
    __shared__ float sv[256];
    __shared__ int si[256];
    sv[tid] = best; si[tid] = bi;
    __syncthreads();
    for (int o = 128; o > 0; o >>= 1) {
        if (tid < o) {
            if (sv[tid + o] > sv[tid] || (sv[tid + o] == sv[tid] && si[tid + o] < si[tid])) {
                sv[tid] = sv[tid + o]; si[tid] = si[tid + o];
            }
        }
        __syncthreads();
    }
    if (tid == 0) preds[row] = (float)si[0];
}

// ---------------- launch ----------------
extern "C" void kernel_launch(void* const* d_in, const int* in_sizes, int n_in,
                              void* d_out, int out_size) {
    const int*   actions = (const int*)d_in[0];
    const float* embed = (const float*)d_in[1];
    const float* aW = (const float*)d_in[2];
    const float* aU = (const float*)d_in[3];
    const float* ab = (const float*)d_in[4];
    const float* bW = (const float*)d_in[5];
    const float* bU = (const float*)d_in[6];
    const float* bb = (const float*)d_in[7];
    const float* sW = (const float*)d_in[8];
    const float* sU = (const float*)d_in[9];
    const float* sb = (const float*)d_in[10];
    const float* rW = (const float*)d_in[11];
    const float* rU = (const float*)d_in[12];
    const float* rb = (const float*)d_in[13];
    const float* Wc = (const float*)d_in[14];
    const float* bc = (const float*)d_in[15];
    const float* Wp = (const float*)d_in[16];
    const float* bp = (const float*)d_in[17];

    float* outf = (float*)d_out;
    size_t nl = (size_t)BB * TT * VV;
    float* preds = nullptr;
    float* logits;
    if ((size_t)out_size >= nl + (size_t)BB * TT) {
        preds = outf;
        logits = outf + BB * TT;
    } else {
        logits = outf;
    }

    control_kernel<<<1, 32>>>(actions);
    tokxw_kernel<<<dim3(NTOK, 4), 192>>>(embed, aW, ab, bW, bb, sW, sb, rW, rb);

    // smem: sm_v + hs + bufh/ah/hred + s_hu + s_xw + part(8*768) + p_s/p_ah/p_b
    size_t shfloats = (size_t)SS * HH * 2 + HH * 3 + H3 * 2 + 8 * H3 + HH * 3;
    size_t shbytes = shfloats * sizeof(float);
    cudaFuncSetAttribute(main_kernel, cudaFuncAttributeMaxDynamicSharedMemorySize, (int)shbytes);
    main_kernel<<<BB, 256, shbytes>>>(aU, bU, sU, rU, sW, sb, rW, rb, Wc, bc);

    dim3 gg((VV + GBN - 1) / GBN, (BB * TT + GBM - 1) / GBM);
    gemm_kernel<<<gg, 256>>>(Wp, bp, logits);
    if (preds) argmax_kernel<<<BB * TT, 256>>>(logits, preds);
}

// round 5
// speedup vs baseline: 4.9346x; 1.0386x over previous
#include <cuda_runtime.h>
#include <math.h>

#define BB 32
#define SS 32
#define TT 31
#define HH 256
#define H3 768
#define VV 12000
#define NTOK 32
#define BOUND 16
#define ATP 1024   // padded row length of g_attT

// ---------------- metadata (written by control kernel) ----------------
__device__ signed char g_la[TT][BB];
__device__ signed char g_npop[TT][BB];
__device__ signed char g_pop_slot[TT][BB][SS];
__device__ signed char g_pop_tok[TT][BB][SS];
__device__ signed char g_spush_slot[TT][BB];   // -1 none
__device__ signed char g_spush_tok[TT][BB];    // -1 = rfinal value, >=0 token
__device__ signed char g_bpush_tok[TT][BB];    // -1 none
__device__ signed char g_stop[TT][BB];         // stack top after step

// precomputed token xw tables: set 0=a,1=b,2=s,3=r
__device__ __align__(16) float g_tokxw[4][NTOK][H3];
// attention outputs TRANSPOSED: [hidden c][row], row = b*TT + t; zero-init padding
__device__ __align__(16) float g_attT[HH][ATP];

// ---------------- small asm helpers ----------------
__device__ __forceinline__ unsigned long long pk2(float lo, float hi) {
    unsigned long long r;
    asm("mov.b64 %0, {%1, %2};" : "=l"(r) : "f"(lo), "f"(hi));
    return r;
}
__device__ __forceinline__ void upk2(float& lo, float& hi, unsigned long long v) {
    asm("mov.b64 {%0, %1}, %2;" : "=f"(lo), "=f"(hi) : "l"(v));
}
__device__ __forceinline__ void ffma2(unsigned long long& d, unsigned long long a,
                                      unsigned long long b) {
    asm("fma.rn.f32x2 %0, %1, %2, %3;" : "=l"(d) : "l"(a), "l"(b), "l"(d));
}
__device__ __forceinline__ unsigned smem_u32(const void* p) {
    return (unsigned)__cvta_generic_to_shared(p);
}
__device__ __forceinline__ void st_peer(unsigned addr, unsigned peer, float v) {
    unsigned pa;
    asm volatile("mapa.shared::cluster.u32 %0, %1, %2;" : "=r"(pa) : "r"(addr), "r"(peer));
    asm volatile("st.shared::cluster.f32 [%0], %1;" :: "r"(pa), "f"(v) : "memory");
}
#define CLUSTER_SYNC() do { \
    asm volatile("barrier.cluster.arrive.aligned;" ::: "memory"); \
    asm volatile("barrier.cluster.wait.aligned;" ::: "memory"); } while (0)

#define CP16(dst, src) \
    asm volatile("cp.async.cg.shared.global [%0], [%1], 16;" :: "r"(dst), "l"(src))
#define CP_COMMIT() asm volatile("cp.async.commit_group;" ::: "memory")

// ---------------- control kernel: pure integer RNNG simulation ----------------
__global__ void control_kernel(const int* __restrict__ actions) {
    int b = threadIdx.x;
    int st = -1, tt_ = -1, bt = 0, acc = 1;  // bt=0 after initial buffer push
    signed char tm[SS];
    signed char stok[SS];

    for (int t = 0; t < TT; t++) {
        int a = actions[b * SS + t];
        int la = a * acc;
        int is_red = (la == 2) ? 1 : 0;
        int is_nt  = (la > 2 && la < BOUND) ? 1 : 0;
        int is_gen = (la >= BOUND) ? 1 : 0;

        int np = 0;
        int ir = is_red, aok = 1;
        for (int i = 0; i < SS; i++) {
            if (!(ir && aok)) break;
            int can1 = (st >= 0);
            int pslot = -1;
            if (can1) { pslot = st; st--; }
            aok = aok & can1;
            int tag = 0;
            if (ir && aok) {
                int can2 = (tt_ >= 0);
                if (can2) { tag = tm[tt_]; tt_--; }
                aok = aok & can2;
            }
            int outm = ir & aok;
            if (outm) {
                g_pop_slot[t][b][np] = (signed char)pslot;
                g_pop_tok[t][b][np]  = stok[pslot];
                np++;
            }
            ir = (ir - tag) * aok;
        }
        int racc = aok;
        int sslot = -1, stokv = -2;
        if (is_red && racc) {
            int can = (st + 1 < SS);
            if (can) { st++; sslot = st; stokv = -1; stok[st] = -1; }
            racc &= can;
            if (racc) {
                int can2 = (tt_ + 1 < SS);
                if (can2) { tt_++; tm[tt_] = 0; }
                racc &= can2;
            }
        }
        unsigned ball = __ballot_sync(0xffffffffu, is_red);
        int tot = np;
        for (int o = 16; o > 0; o >>= 1) tot += __shfl_xor_sync(0xffffffffu, tot, o);
        int red_mult = 1;
        if (ball) red_mult = (tot == 0) ? 0 : racc;
        acc *= red_mult;

        if (is_nt) {
            int s5 = (st + 1 < SS);
            if (s5) { st++; stok[st] = (signed char)la; sslot = st; stokv = la; }
            acc *= s5;
            if (s5) {
                int s6 = (tt_ + 1 < SS);
                if (s6) { tt_++; tm[tt_] = 1; }
                acc *= s6;
            }
        }
        int bpush = -1;
        if (is_gen) {
            int s7 = (st + 1 < SS);
            if (s7) { st++; stok[st] = (signed char)la; sslot = st; stokv = la; }
            acc *= s7;
            int s8 = 1;
            if (s7) {
                s8 = (tt_ + 1 < SS);
                if (s8) { tt_++; tm[tt_] = 0; }
                acc *= s8;
            }
            if (s7 && s8) {
                int s9 = (bt + 1 < SS);
                if (s9) { bt++; bpush = la; }
                acc *= s9;
            }
        }
        g_bpush_tok[t][b]  = (signed char)bpush;
        g_la[t][b]         = (signed char)la;
        g_npop[t][b]       = (signed char)np;
        g_spush_slot[t][b] = (signed char)sslot;
        g_spush_tok[t][b]  = (signed char)stokv;
        g_stop[t][b]       = (signed char)st;
    }
}

// ---------------- token xw tables ----------------
__global__ void tokxw_kernel(const float* __restrict__ embed,
                             const float* __restrict__ aW, const float* __restrict__ ab,
                             const float* __restrict__ bW, const float* __restrict__ bb,
                             const float* __restrict__ sW, const float* __restrict__ sb,
                             const float* __restrict__ rW, const float* __restrict__ rb) {
    int tok = blockIdx.x;
    int set = blockIdx.y;
    const float* W  = (set == 0) ? aW : (set == 1) ? bW : (set == 2) ? sW : rW;
    const float* bi = (set == 0) ? ab : (set == 1) ? bb : (set == 2) ? sb : rb;
    int tid = threadIdx.x;  // 192 threads, 1 float4 col each
    const float4* W4 = (const float4*)W;
    float4 acc = __ldg((const float4*)bi + tid);
    const float* x = embed + (size_t)tok * HH;
#pragma unroll 8
    for (int k = 0; k < HH; k++) {
        float xk = __ldg(x + k);
        float4 w = __ldg(W4 + k * 192 + tid);
        acc.x += xk * w.x; acc.y += xk * w.y; acc.z += xk * w.z; acc.w += xk * w.w;
    }
    ((float4*)(&g_tokxw[set][tok][0]))[tid] = acc;
}

// ---------------- half matvec: this CTA's 384 of 768 cols ----------------
// M row-major [256,768]. Owned float4 cols: g*64 + rank*32 + l  (g=0..2).
// out[] is the full-length [768] array; only owned cols written.
__device__ __forceinline__ void mv_half(const float* __restrict__ M, const float* __restrict__ x,
                                        float* out, const float* __restrict__ bias,
                                        int tid, int rank, float* part) {
    __syncthreads();  // protect part + ensure x stable
    int w = tid >> 5, l = tid & 31;
    const float4* M4 = (const float4*)M + (size_t)(w * 32) * 192 + rank * 32;
    const float* xs = x + w * 32;
    float4 a0 = make_float4(0.f, 0.f, 0.f, 0.f), a1 = a0, a2 = a0;
#pragma unroll 2
    for (int k = 0; k < 32; k++) {
        float xk = xs[k];
        const float4* row = M4 + k * 192;
        float4 m0 = __ldg(row + l);
        float4 m1 = __ldg(row + 64 + l);
        float4 m2 = __ldg(row + 128 + l);
        a0.x += xk * m0.x; a0.y += xk * m0.y; a0.z += xk * m0.z; a0.w += xk * m0.w;
        a1.x += xk * m1.x; a1.y += xk * m1.y; a1.z += xk * m1.z; a1.w += xk * m1.w;
        a2.x += xk * m2.x; a2.y += xk * m2.y; a2.z += xk * m2.z; a2.w += xk * m2.w;
    }
    float4* p4 = (float4*)part + w * 96;
    p4[l] = a0; p4[32 + l] = a1; p4[64 + l] = a2;
    __syncthreads();
    if (tid < 128) {
#pragma unroll
        for (int g = 0; g < 3; g++) {
            int c = g * 256 + rank * 128 + tid;
            float s = bias ? __ldg(bias + c) : 0.f;
#pragma unroll
            for (int w2 = 0; w2 < 8; w2++) s += part[w2 * 384 + g * 128 + tid];
            out[c] = s;
        }
    }
    // no trailing sync: consumers are the same tid<128 threads
}

// half piece matvec: out[tid<128] = (x @ Wpiece)[rank*128 + tid], Wpiece [256,256]
__device__ __forceinline__ void piece_half(const float* __restrict__ W, const float* __restrict__ x,
                                           float* out, int tid, int rank, float* part) {
    __syncthreads();
    int w = tid >> 5, l = tid & 31;
    const float4* W4 = (const float4*)W + (size_t)(w * 32) * 64 + rank * 32;
    const float* xs = x + w * 32;
    float4 a = make_float4(0.f, 0.f, 0.f, 0.f);
#pragma unroll 4
    for (int k = 0; k < 32; k++) {
        float xk = xs[k];
        float4 m = __ldg(W4 + k * 64 + l);
        a.x += xk * m.x; a.y += xk * m.y; a.z += xk * m.z; a.w += xk * m.w;
    }
    ((float4*)part)[w * 32 + l] = a;
    __syncthreads();
    if (tid < 128) {
        float s = 0.f;
#pragma unroll
        for (int w2 = 0; w2 < 8; w2++) s += part[w2 * 128 + tid];
        out[tid] = s;
    }
}

__device__ __forceinline__ float sigm(float v) { return 1.f / (1.f + expf(-v)); }

// ---------------- main kernel: 2-CTA cluster per batch lane ----------------
extern __shared__ float smem_f[];
__global__ __launch_bounds__(256) __cluster_dims__(2, 1, 1)
void main_kernel(
    const float* __restrict__ aU, const float* __restrict__ bU,
    const float* __restrict__ sU, const float* __restrict__ rU,
    const float* __restrict__ sW, const float* __restrict__ sb,
    const float* __restrict__ rW, const float* __restrict__ rb,
    const float* __restrict__ Wc, const float* __restrict__ bc) {
    int tid = threadIdx.x;
    int b = blockIdx.x >> 1;
    int rank = blockIdx.x & 1;
    unsigned peer = (unsigned)(rank ^ 1);

    float* sm_v = smem_f;            // [32][256] stack values (full replica)
    float* hs   = sm_v + SS * HH;    // [32][256] hidden-state stack (full replica)
    float* bufh = hs + SS * HH;      // [256]
    float* ah   = bufh + HH;         // [256]
    float* hred = ah + HH;           // [256]
    float* s_hu = hred + HH;         // [768] (owned cols only valid)
    float* s_xw = s_hu + H3;         // [768]
    float* part = s_xw + H3;         // [8*384] scratch
    float* p_s  = part + 8 * 384;    // [128] local half of attention pieces
    float* p_ah = p_s + 128;         // [128]
    float* p_b  = p_ah + 128;        // [128]

    unsigned base_u32 = smem_u32(smem_f);
    unsigned hs_a   = base_u32 + (unsigned)((char*)hs - (char*)smem_f);
    unsigned bufh_a = base_u32 + (unsigned)((char*)bufh - (char*)smem_f);
    unsigned ah_a   = base_u32 + (unsigned)((char*)ah - (char*)smem_f);
    unsigned hred_a = base_u32 + (unsigned)((char*)hred - (char*)smem_f);

    // initial buffer push: bufh = GRU_b(embed[1], h=0)  -> h = sigm(xz)*tanh(xn)
    {
        const float* xw = &g_tokxw[1][1][0];
        bufh[tid] = sigm(xw[tid]) * tanhf(xw[2 * HH + tid]);
        if (tid < 128) p_s[tid] = 0.f;
    }
    __syncthreads();

    int prev_stop = -1;

    for (int t = 0; t < TT; t++) {
        int la    = g_la[t][b];
        int np    = g_npop[t][b];
        int sslot = g_spush_slot[t][b];
        int stokv = g_spush_tok[t][b];
        int bpush = g_bpush_tok[t][b];
        int stop  = g_stop[t][b];

        // ---- reduce chain ----
        for (int i = 0; i < np; i++) {
            int slot = g_pop_slot[t][b][i];
            int tok  = g_pop_tok[t][b][i];
            if (tok >= 0 && i == 0) {
                // full-local: h = sigm(xz)*tanh(xn); both CTAs compute all 256
                const float* xw = &g_tokxw[3][tok][0];
                __syncthreads();
                hred[tid] = sigm(xw[tid]) * tanhf(xw[2 * HH + tid]);
                __syncthreads();
            } else {
                const float* xw;
                if (tok >= 0) xw = &g_tokxw[3][tok][0];
                else { mv_half(rW, &sm_v[slot * HH], s_xw, rb, tid, rank, part); xw = s_xw; }
                if (i > 0) mv_half(rU, hred, s_hu, nullptr, tid, rank, part);
                if (tid < 128) {
                    int c = rank * 128 + tid;
                    float hz = 0.f, hr = 0.f, hn = 0.f, hp = 0.f;
                    if (i > 0) { hz = s_hu[c]; hr = s_hu[HH + c]; hn = s_hu[2 * HH + c]; hp = hred[c]; }
                    float z = sigm(xw[c] + hz);
                    float r = sigm(xw[HH + c] + hr);
                    float n = tanhf(xw[2 * HH + c] + r * hn);
                    float h = (1.f - z) * hp + z * n;
                    hred[c] = h;
                    st_peer(hred_a + (unsigned)c * 4, peer, h);
                }
                CLUSTER_SYNC();
            }
        }

        // ---- stack push preparation ----
        const float* xw_s = nullptr;
        if (sslot >= 0) {
            if (stokv >= 0) {
                xw_s = &g_tokxw[2][stokv][0];
            } else {
                __syncthreads();
                sm_v[sslot * HH + tid] = hred[tid];   // full hred is local post-chain-sync
                mv_half(sW, hred, s_xw, sb, tid, rank, part);
                xw_s = s_xw;
            }
            if (sslot > 0) mv_half(sU, &hs[(sslot - 1) * HH], s_hu, nullptr, tid, rank, part);
            if (tid < 128) {
                int c = rank * 128 + tid;
                float hz = 0.f, hr = 0.f, hn = 0.f, hp = 0.f;
                if (sslot > 0) {
                    hz = s_hu[c]; hr = s_hu[HH + c]; hn = s_hu[2 * HH + c];
                    hp = hs[(sslot - 1) * HH + c];
                }
                float z = sigm(xw_s[c] + hz);
                float r = sigm(xw_s[HH + c] + hr);
                float n = tanhf(xw_s[2 * HH + c] + r * hn);
                float h = (1.f - z) * hp + z * n;
                hs[sslot * HH + c] = h;
                st_peer(hs_a + (unsigned)(sslot * HH + c) * 4, peer, h);
            }
        }

        // ---- buffer push (GEN) ----
        if (bpush >= 0) {
            mv_half(bU, bufh, s_hu, nullptr, tid, rank, part);
            if (tid < 128) {
                int c = rank * 128 + tid;
                const float* xw = &g_tokxw[1][bpush][0];
                float z = sigm(xw[c] + s_hu[c]);
                float r = sigm(xw[HH + c] + s_hu[HH + c]);
                float n = tanhf(xw[2 * HH + c] + r * s_hu[2 * HH + c]);
                float h = (1.f - z) * bufh[c] + z * n;
                bufh[c] = h;
                st_peer(bufh_a + (unsigned)c * 4, peer, h);
            }
        }

        // ---- action GRU ----
        if (t > 0) {
            mv_half(aU, ah, s_hu, nullptr, tid, rank, part);
            if (tid < 128) {
                int c = rank * 128 + tid;
                const float* xw = &g_tokxw[0][la][0];
                float z = sigm(xw[c] + s_hu[c]);
                float r = sigm(xw[HH + c] + s_hu[HH + c]);
                float n = tanhf(xw[2 * HH + c] + r * s_hu[2 * HH + c]);
                float h = (1.f - z) * ah[c] + z * n;
                ah[c] = h;
                st_peer(ah_a + (unsigned)c * 4, peer, h);
            }
        } else {
            __syncthreads();
            const float* xw = &g_tokxw[0][la][0];
            ah[tid] = sigm(xw[tid]) * tanhf(xw[2 * HH + tid]);
        }
        CLUSTER_SYNC();   // all state halves exchanged; full states visible

        // ---- attention with dirty-tracked [256,256] pieces of Wc ----
        {
            bool s_dirty = (stop != prev_stop) || (sslot >= 0);
            if (s_dirty) {
                if (stop < 0) {
                    __syncthreads();
                    if (tid < 128) p_s[tid] = 0.f;
                } else {
                    piece_half(Wc, &hs[stop * HH], p_s, tid, rank, part);
                }
            }
            piece_half(Wc + (size_t)HH * HH, ah, p_ah, tid, rank, part);
            if (t == 0 || bpush >= 0)
                piece_half(Wc + (size_t)2 * HH * HH, bufh, p_b, tid, rank, part);
            if (tid < 128) {
                int c = rank * 128 + tid;
                float v = p_s[tid] + p_ah[tid] + p_b[tid] + __ldg(bc + c);
                g_attT[c][b * TT + t] = tanhf(v);
            }
            prev_stop = stop;
        }
        CLUSTER_SYNC();   // protect state reads from next step's peer writes
    }
}

// ---------------- logits GEMM: cp.async double-buffered, f32x2 FFMA ----------------
#define GBM 128
#define GBN 128
#define GBK 16
__global__ __launch_bounds__(256, 2) void gemm_kernel(const float* __restrict__ Wp,
                                                      const float* __restrict__ bp,
                                                      float* __restrict__ out) {
    __shared__ float As[2][GBK][GBM];  // 16 KB
    __shared__ float Bs[2][GBK][GBN];  // 16 KB
    int tid = threadIdx.x;
    int c0 = blockIdx.x * GBN;
    int row0 = blockIdx.y * GBM;
    const int MROWS = BB * TT;  // 992
    const float* attT = &g_attT[0][0];

    unsigned sA = smem_u32(&As[0][0][0]);
    unsigned sB = smem_u32(&Bs[0][0][0]);

    int ty = tid >> 4, tx = tid & 15;

    unsigned long long accp[8][4];
#pragma unroll
    for (int i = 0; i < 8; i++)
#pragma unroll
        for (int j = 0; j < 4; j++) accp[i][j] = 0ull;

    const int NTILE = HH / GBK;  // 16

    // tile issue helper (inlined twice)
#define ISSUE_TILE(buf, kk) do {                                              \
        _Pragma("unroll")                                                     \
        for (int i_ = 0; i_ < 2; i_++) {                                      \
            int idx_ = tid * 2 + i_;                                          \
            int k_ = idx_ >> 5;                                               \
            int q_ = idx_ & 31;                                               \
            unsigned da_ = sA + (unsigned)((((buf) * GBK + k_) * GBM + q_ * 4) * 4); \
            CP16(da_, attT + (size_t)((kk) + k_) * ATP + row0 + q_ * 4);      \
            int gc_ = c0 + q_ * 4;                                            \
            if (gc_ + 3 < VV) {                                               \
                unsigned db_ = sB + (unsigned)((((buf) * GBK + k_) * GBN + q_ * 4) * 4); \
                CP16(db_, Wp + (size_t)((kk) + k_) * VV + gc_);               \
            } else {                                                          \
                float4 z4_ = make_float4(0.f, 0.f, 0.f, 0.f);                 \
                *(float4*)&Bs[buf][k_][q_ * 4] = z4_;                         \
            }                                                                 \
        }                                                                     \
        CP_COMMIT();                                                          \
    } while (0)

    ISSUE_TILE(0, 0);
    for (int tIdx = 0; tIdx < NTILE; tIdx++) {
        int buf = tIdx & 1;
        if (tIdx + 1 < NTILE) {
            ISSUE_TILE((tIdx + 1) & 1, (tIdx + 1) * GBK);
            asm volatile("cp.async.wait_group 1;" ::: "memory");
        } else {
            asm volatile("cp.async.wait_group 0;" ::: "memory");
        }
        __syncthreads();
#pragma unroll
        for (int k = 0; k < GBK; k++) {
            float4 a01 = *((const float4*)&As[buf][k][ty * 8]);
            float4 a23 = *((const float4*)&As[buf][k][ty * 8 + 4]);
            float4 b01 = *((const float4*)&Bs[buf][k][tx * 8]);
            float4 b23 = *((const float4*)&Bs[buf][k][tx * 8 + 4]);
            unsigned long long brp[4];
            brp[0] = pk2(b01.x, b01.y); brp[1] = pk2(b01.z, b01.w);
            brp[2] = pk2(b23.x, b23.y); brp[3] = pk2(b23.z, b23.w);
            float ar[8] = {a01.x, a01.y, a01.z, a01.w, a23.x, a23.y, a23.z, a23.w};
#pragma unroll
            for (int i = 0; i < 8; i++) {
                unsigned long long ap = pk2(ar[i], ar[i]);
                ffma2(accp[i][0], ap, brp[0]);
                ffma2(accp[i][1], ap, brp[1]);
                ffma2(accp[i][2], ap, brp[2]);
                ffma2(accp[i][3], ap, brp[3]);
            }
        }
        __syncthreads();
    }

    float bias[8];
#pragma unroll
    for (int j = 0; j < 8; j++) {
        int gc = c0 + tx * 8 + j;
        bias[j] = (gc < VV) ? __ldg(bp + gc) : 0.f;
    }
#pragma unroll
    for (int i = 0; i < 8; i++) {
        int grow = row0 + ty * 8 + i;
        if (grow >= MROWS) continue;
        int gc = c0 + tx * 8;
        float acc[8];
#pragma unroll
        for (int j = 0; j < 4; j++) upk2(acc[2 * j], acc[2 * j + 1], accp[i][j]);
        if (gc + 7 < VV) {
            float4 o0 = make_float4(acc[0] + bias[0], acc[1] + bias[1],
                                    acc[2] + bias[2], acc[3] + bias[3]);
            float4 o1 = make_float4(acc[4] + bias[4], acc[5] + bias[5],
                                    acc[6] + bias[6], acc[7] + bias[7]);
            *((float4*)(out + (size_t)grow * VV + gc)) = o0;
            *((float4*)(out + (size_t)grow * VV + gc + 4)) = o1;
        } else {
#pragma unroll
            for (int j = 0; j < 8; j++)
                if (gc + j < VV) out[(size_t)grow * VV + gc + j] = acc[j] + bias[j];
        }
    }
}

// ---------------- argmax per row ----------------
__global__ void argmax_kernel(const float* __restrict__ logits, float* __restrict__ preds) {
    int row = blockIdx.x;
    int tid = threadIdx.x;
    const float* p = logits + (size_t)row * VV;
    float best = -3.4e38f;
    int bi = VV;
    for (int c = tid; c < VV; c += 256) {
        float v = p[c];
        if (v > best) { best = v; bi = c; }
    }
    __shared__ float sv[256];
    __shared__ int si[256];
    sv[tid] = best; si[tid] = bi;
    __syncthreads();
    for (int o = 128; o > 0; o >>= 1) {
        if (tid < o) {
            if (sv[tid + o] > sv[tid] || (sv[tid + o] == sv[tid] && si[tid + o] < si[tid])) {
                sv[tid] = sv[tid + o]; si[tid] = si[tid + o];
            }
        }
        __syncthreads();
    }
    if (tid == 0) preds[row] = (float)si[0];
}

// ---------------- launch ----------------
extern "C" void kernel_launch(void* const* d_in, const int* in_sizes, int n_in,
                              void* d_out, int out_size) {
    const int*   actions = (const int*)d_in[0];
    const float* embed = (const float*)d_in[1];
    const float* aW = (const float*)d_in[2];
    const float* aU = (const float*)d_in[3];
    const float* ab = (const float*)d_in[4];
    const float* bW = (const float*)d_in[5];
    const float* bU = (const float*)d_in[6];
    const float* bb = (const float*)d_in[7];
    const float* sW = (const float*)d_in[8];
    const float* sU = (const float*)d_in[9];
    const float* sb = (const float*)d_in[10];
    const float* rW = (const float*)d_in[11];
    const float* rU = (const float*)d_in[12];
    const float* rb = (const float*)d_in[13];
    const float* Wc = (const float*)d_in[14];
    const float* bc = (const float*)d_in[15];
    const float* Wp = (const float*)d_in[16];
    const float* bp = (const float*)d_in[17];

    float* outf = (float*)d_out;
    size_t nl = (size_t)BB * TT * VV;
    float* preds = nullptr;
    float* logits;
    if ((size_t)out_size >= nl + (size_t)BB * TT) {
        preds = outf;
        logits = outf + BB * TT;
    } else {
        logits = outf;
    }

    control_kernel<<<1, 32>>>(actions);
    tokxw_kernel<<<dim3(NTOK, 4), 192>>>(embed, aW, ab, bW, bb, sW, sb, rW, rb);

    // smem: sm_v(32*256) + hs(32*256) + bufh/ah/hred(3*256) + s_hu/s_xw(2*768)
    //       + part(8*384) + p_s/p_ah/p_b(3*128)
    size_t shfloats = (size_t)SS * HH * 2 + HH * 3 + H3 * 2 + 8 * 384 + 3 * 128;
    size_t shbytes = shfloats * sizeof(float);
    cudaFuncSetAttribute(main_kernel, cudaFuncAttributeMaxDynamicSharedMemorySize, (int)shbytes);
    main_kernel<<<2 * BB, 256, shbytes>>>(aU, bU, sU, rU, sW, sb, rW, rb, Wc, bc);

    dim3 gg((VV + GBN - 1) / GBN, (BB * TT + GBM - 1) / GBM);
    gemm_kernel<<<gg, 256>>>(Wp, bp, logits);
    if (preds) argmax_kernel<<<BB * TT, 256>>>(logits, preds);
}